// round 1
// baseline (speedup 1.0000x reference)
#include <cuda_runtime.h>
#include <math.h>
#include <stdint.h>

// ---------------------------------------------------------------------------
// Problem constants
// ---------------------------------------------------------------------------
#define GQ      32
#define NODES0  1024
#define NT_MAX  (GQ * NODES0)      // 32768
#define E_TOT   (GQ * 16384)       // 524288
#define HF      128
#define EPSB    1e-5f

// per-layer node counts
// ntin : {32768, 26240, 20992, 16800}
// n    : {1024, 820, 656, 525}
// k    : {820, 656, 525, 420}

// ---------------------------------------------------------------------------
// Device scratch (no allocation allowed)
// ---------------------------------------------------------------------------
__device__ float g_h0[NT_MAX * HF];     // ping (h_in / hp)
__device__ float g_h1[NT_MAX * HF];     // pong (h_pre / post-BN h)
__device__ float g_agg[NT_MAX * HF];    // aggregate -> mean
__device__ float g_cnt[NT_MAX];
__device__ float g_score[NT_MAX];
__device__ int   g_perm[NT_MAX];
__device__ int   g_map[NT_MAX];
__device__ int   g_src[E_TOT];
__device__ int   g_dst[E_TOT];
__device__ float g_valid[E_TOT];
__device__ float g_colsum[HF];
__device__ float g_colsq[HF];
__device__ float g_scale[HF];
__device__ float g_shift[HF];
__device__ float g_invp[1];
__device__ float g_flat[GQ * 1024];
__device__ float g_hd[GQ * 512];

// ---------------------------------------------------------------------------
// Kernels
// ---------------------------------------------------------------------------
__global__ void init_edges_k(const int* __restrict__ ei,
                             int* __restrict__ src, int* __restrict__ dst,
                             float* __restrict__ valid)
{
    int e = blockIdx.x * blockDim.x + threadIdx.x;
    if (e >= E_TOT) return;
    src[e] = ei[e];
    dst[e] = ei[E_TOT + e];
    valid[e] = 1.0f;
}

// one warp per edge; 4 floats per lane
__global__ void scatter_agg_k(const float* __restrict__ h,
                              const int* __restrict__ src, const int* __restrict__ dst,
                              const float* __restrict__ valid,
                              float* __restrict__ agg, float* __restrict__ cnt)
{
    int w = (blockIdx.x * blockDim.x + threadIdx.x) >> 5;
    int lane = threadIdx.x & 31;
    if (w >= E_TOT) return;
    float v = __ldg(valid + w);
    if (v == 0.0f) return;
    int s = __ldg(src + w), d = __ldg(dst + w);
    const float* hs = h + (size_t)s * HF;
    float* ad = agg + (size_t)d * HF;
#pragma unroll
    for (int i = 0; i < 4; i++) {
        int f = lane + i * 32;
        atomicAdd(ad + f, __ldg(hs + f));
    }
    if (lane == 0) atomicAdd(cnt + d, v);
}

__global__ void mean_div_k(float* __restrict__ agg, const float* __restrict__ cnt, int total)
{
    int i = blockIdx.x * blockDim.x + threadIdx.x;
    if (i >= total) return;
    float c = cnt[i >> 7];
    agg[i] = agg[i] / fmaxf(c, 1.0f);
}

// C[M,128] = [A1 | A2] (M x 256) @ [B1 ; B2] (256 x 128) + bias
__global__ __launch_bounds__(256) void gemm_dual_k(
    const float* __restrict__ A1, const float* __restrict__ A2,
    const float* __restrict__ B1, const float* __restrict__ B2,
    const float* __restrict__ bias, float* __restrict__ C, int M)
{
    __shared__ __align__(16) float As[16][128];
    __shared__ __align__(16) float Bs[16][128];
    const int tid = threadIdx.x;
    const int tx = tid & 15;     // 0..15 -> col*8
    const int ty = tid >> 4;     // 0..15 -> row*8
    const int row0 = blockIdx.x * 128;

    float acc[8][8];
#pragma unroll
    for (int i = 0; i < 8; i++)
#pragma unroll
        for (int j = 0; j < 8; j++) acc[i][j] = 0.0f;

    for (int k0 = 0; k0 < 256; k0 += 16) {
        const float* Asrc = (k0 < 128) ? A1 : A2;
        const float* Bsrc = (k0 < 128) ? B1 : B2;
        const int kbase = (k0 < 128) ? k0 : (k0 - 128);
#pragma unroll
        for (int i = 0; i < 2; i++) {
            int task = tid + i * 256;           // 0..511
            int r = task >> 2;                  // 0..127
            int kq = (task & 3) << 2;           // 0,4,8,12
            float4 v = make_float4(0.f, 0.f, 0.f, 0.f);
            int grow = row0 + r;
            if (grow < M)
                v = *(const float4*)(Asrc + (size_t)grow * 128 + kbase + kq);
            As[kq + 0][r] = v.x; As[kq + 1][r] = v.y;
            As[kq + 2][r] = v.z; As[kq + 3][r] = v.w;
        }
#pragma unroll
        for (int i = 0; i < 2; i++) {
            int task = tid + i * 256;
            int kr = task >> 5;                 // 0..15
            int nc = (task & 31) << 2;          // 0..124
            *(float4*)&Bs[kr][nc] =
                *(const float4*)(Bsrc + (size_t)(kbase + kr) * 128 + nc);
        }
        __syncthreads();
#pragma unroll
        for (int k = 0; k < 16; k++) {
            float a[8], b[8];
            *(float4*)&a[0] = *(float4*)&As[k][ty * 8];
            *(float4*)&a[4] = *(float4*)&As[k][ty * 8 + 4];
            *(float4*)&b[0] = *(float4*)&Bs[k][tx * 8];
            *(float4*)&b[4] = *(float4*)&Bs[k][tx * 8 + 4];
#pragma unroll
            for (int i = 0; i < 8; i++)
#pragma unroll
                for (int j = 0; j < 8; j++)
                    acc[i][j] += a[i] * b[j];
        }
        __syncthreads();
    }

    float bcol[8];
#pragma unroll
    for (int j = 0; j < 8; j++) bcol[j] = bias[tx * 8 + j];
#pragma unroll
    for (int i = 0; i < 8; i++) {
        int r = row0 + ty * 8 + i;
        if (r < M) {
            float4 o0 = make_float4(acc[i][0] + bcol[0], acc[i][1] + bcol[1],
                                    acc[i][2] + bcol[2], acc[i][3] + bcol[3]);
            float4 o1 = make_float4(acc[i][4] + bcol[4], acc[i][5] + bcol[5],
                                    acc[i][6] + bcol[6], acc[i][7] + bcol[7]);
            *(float4*)(C + (size_t)r * 128 + tx * 8) = o0;
            *(float4*)(C + (size_t)r * 128 + tx * 8 + 4) = o1;
        }
    }
}

// column sums / sumsq partials (128 threads = 128 features, 256 rows per block)
__global__ void bn_partial_k(const float* __restrict__ h, int M,
                             float* __restrict__ colsum, float* __restrict__ colsq)
{
    int f = threadIdx.x;
    int r0 = blockIdx.x * 256;
    int r1 = min(r0 + 256, M);
    float s = 0.f, q = 0.f;
    for (int r = r0; r < r1; r++) {
        float v = h[(size_t)r * HF + f];
        s += v; q += v * v;
    }
    atomicAdd(&colsum[f], s);
    atomicAdd(&colsq[f], q);
}

__global__ void bn_finalize_k(const float* __restrict__ colsum, const float* __restrict__ colsq,
                              float invM,
                              const float* __restrict__ g, const float* __restrict__ be,
                              const float* __restrict__ p,
                              float* __restrict__ scale, float* __restrict__ shift,
                              float* __restrict__ invp)
{
    __shared__ float red[128];
    int f = threadIdx.x;
    float mu = colsum[f] * invM;
    float var = colsq[f] * invM - mu * mu;
    float rstd = rsqrtf(var + EPSB);
    float sc = rstd * g[f];
    scale[f] = sc;
    shift[f] = be[f] - mu * sc;
    float pv = p[f];
    red[f] = pv * pv;
    __syncthreads();
    for (int o = 64; o > 0; o >>= 1) {
        if (f < o) red[f] += red[f + o];
        __syncthreads();
    }
    if (f == 0) invp[0] = rsqrtf(red[0]);
}

// in-place BN+ReLU on h, plus score = (h . p) * invp  (one warp per row)
__global__ void bn_relu_score_k(float* __restrict__ h, int M,
                                const float* __restrict__ scale, const float* __restrict__ shift,
                                const float* __restrict__ p, const float* __restrict__ invp,
                                float* __restrict__ score)
{
    int w = (blockIdx.x * blockDim.x + threadIdx.x) >> 5;
    int lane = threadIdx.x & 31;
    if (w >= M) return;
    float* row = h + (size_t)w * HF;
    float acc = 0.f;
#pragma unroll
    for (int i = 0; i < 4; i++) {
        int f = lane + i * 32;
        float v = fmaxf(row[f] * scale[f] + shift[f], 0.f);
        row[f] = v;
        acc += v * p[f];
    }
#pragma unroll
    for (int o = 16; o > 0; o >>= 1) acc += __shfl_xor_sync(0xffffffffu, acc, o);
    if (lane == 0) score[w] = acc * invp[0];
}

// per-graph top-k by full bitonic sort of 1024 (padded) scores
__global__ __launch_bounds__(1024) void topk_k(const float* __restrict__ score,
                                               int n, int k,
                                               int* __restrict__ map, int* __restrict__ perm)
{
    __shared__ float s[1024];
    __shared__ int id[1024];
    int g = blockIdx.x, t = threadIdx.x;
    s[t] = (t < n) ? score[g * n + t] : __int_as_float(0xff800000u); // -inf
    id[t] = t;
    __syncthreads();
    for (int size = 2; size <= 1024; size <<= 1) {
        for (int stride = size >> 1; stride > 0; stride >>= 1) {
            int pos = t ^ stride;
            if (pos > t) {
                bool desc = ((t & size) == 0);
                float s1 = s[t], s2 = s[pos];
                if (desc ? (s1 < s2) : (s1 > s2)) {
                    s[t] = s2; s[pos] = s1;
                    int tmp = id[t]; id[t] = id[pos]; id[pos] = tmp;
                }
            }
            __syncthreads();
        }
    }
    if (t < k) {
        int oldg = g * n + id[t];
        int newg = g * k + t;
        map[oldg] = newg;
        perm[newg] = oldg;
    }
}

// hp[new] = h[perm[new]] * tanh(score[perm[new]])   (one warp per row)
__global__ void gather_gate_k(const float* __restrict__ h, const int* __restrict__ perm,
                              const float* __restrict__ score, float* __restrict__ out, int Mout)
{
    int w = (blockIdx.x * blockDim.x + threadIdx.x) >> 5;
    int lane = threadIdx.x & 31;
    if (w >= Mout) return;
    int old = perm[w];
    float gate = tanhf(score[old]);
    const float* src = h + (size_t)old * HF;
    float* dst = out + (size_t)w * HF;
#pragma unroll
    for (int i = 0; i < 4; i++) {
        int f = lane + i * 32;
        dst[f] = src[f] * gate;
    }
}

// per graph: sum and max over k kept nodes, write into flat[g][off .. off+255]
__global__ void readout_k(const float* __restrict__ hp, int k,
                          float* __restrict__ flat, int off)
{
    int g = blockIdx.x, f = threadIdx.x; // 128 threads
    const float* base = hp + ((size_t)g * k) * HF + f;
    float s = 0.f, m = __int_as_float(0xff800000u);
    for (int r = 0; r < k; r++) {
        float v = base[(size_t)r * HF];
        s += v;
        m = fmaxf(m, v);
    }
    flat[g * 1024 + off + f] = s;
    flat[g * 1024 + off + 128 + f] = m;
}

__global__ void remap_edges_k(int* __restrict__ src, int* __restrict__ dst,
                              float* __restrict__ valid, const int* __restrict__ map)
{
    int e = blockIdx.x * blockDim.x + threadIdx.x;
    if (e >= E_TOT) return;
    int ns = map[src[e]];
    int nd = map[dst[e]];
    float v = valid[e];
    if ((ns | nd) < 0) v = 0.f;
    src[e] = ns < 0 ? 0 : ns;
    dst[e] = nd < 0 ? 0 : nd;
    valid[e] = v;
}

// hd[g] = relu(flat[g] @ Wd1 + bd1)   (block per graph, 512 threads)
__global__ __launch_bounds__(512) void dense1_k(const float* __restrict__ flat,
                                                const float* __restrict__ Wd1,
                                                const float* __restrict__ bd1,
                                                float* __restrict__ hd)
{
    __shared__ float fr[1024];
    int g = blockIdx.x, t = threadIdx.x;
    fr[t] = flat[g * 1024 + t];
    fr[t + 512] = flat[g * 1024 + t + 512];
    __syncthreads();
    float acc = bd1[t];
    for (int kk = 0; kk < 1024; kk++)
        acc += fr[kk] * Wd1[(size_t)kk * 512 + t];
    hd[g * 512 + t] = fmaxf(acc, 0.f);
}

// out[g] = hd[g] @ Wd2 + bd2   (block per graph; 10 warps reduce)
__global__ __launch_bounds__(512) void dense2_k(const float* __restrict__ hd,
                                                const float* __restrict__ Wd2,
                                                const float* __restrict__ bd2,
                                                float* __restrict__ out)
{
    __shared__ float hr[512];
    int g = blockIdx.x, t = threadIdx.x;
    hr[t] = hd[g * 512 + t];
    __syncthreads();
    if (t < 320) {
        int c = t >> 5, lane = t & 31;
        float acc = 0.f;
        for (int kk = lane; kk < 512; kk += 32)
            acc += hr[kk] * Wd2[(size_t)kk * 10 + c];
#pragma unroll
        for (int o = 16; o > 0; o >>= 1) acc += __shfl_down_sync(0xffffffffu, acc, o);
        if (lane == 0) out[g * 10 + c] = acc + bd2[c];
    }
}

// ---------------------------------------------------------------------------
// Host driver
// ---------------------------------------------------------------------------
extern "C" void kernel_launch(void* const* d_in, const int* in_sizes, int n_in,
                              void* d_out, int out_size)
{
    (void)in_sizes; (void)n_in; (void)out_size;

    const float* x  = (const float*)d_in[0];
    const int*   ei = (const int*)d_in[1];
    const float *Wl[4], *Wr[4], *bb[4], *gg[4], *be[4], *pp[4];
    for (int l = 0; l < 4; l++) {
        int b = 3 + 6 * l;
        Wl[l] = (const float*)d_in[b + 0];
        Wr[l] = (const float*)d_in[b + 1];
        bb[l] = (const float*)d_in[b + 2];
        gg[l] = (const float*)d_in[b + 3];
        be[l] = (const float*)d_in[b + 4];
        pp[l] = (const float*)d_in[b + 5];
    }
    const float* Wd1 = (const float*)d_in[27];
    const float* bd1 = (const float*)d_in[28];
    const float* Wd2 = (const float*)d_in[29];
    const float* bd2 = (const float*)d_in[30];
    float* out = (float*)d_out;

    float *h0, *h1, *agg, *cnt, *score, *colsum, *colsq, *scale, *shift, *invp, *flat, *hd, *valid;
    int *src, *dst, *perm, *map;
    cudaGetSymbolAddress((void**)&h0, g_h0);
    cudaGetSymbolAddress((void**)&h1, g_h1);
    cudaGetSymbolAddress((void**)&agg, g_agg);
    cudaGetSymbolAddress((void**)&cnt, g_cnt);
    cudaGetSymbolAddress((void**)&score, g_score);
    cudaGetSymbolAddress((void**)&colsum, g_colsum);
    cudaGetSymbolAddress((void**)&colsq, g_colsq);
    cudaGetSymbolAddress((void**)&scale, g_scale);
    cudaGetSymbolAddress((void**)&shift, g_shift);
    cudaGetSymbolAddress((void**)&invp, g_invp);
    cudaGetSymbolAddress((void**)&flat, g_flat);
    cudaGetSymbolAddress((void**)&hd, g_hd);
    cudaGetSymbolAddress((void**)&valid, g_valid);
    cudaGetSymbolAddress((void**)&src, g_src);
    cudaGetSymbolAddress((void**)&dst, g_dst);
    cudaGetSymbolAddress((void**)&perm, g_perm);
    cudaGetSymbolAddress((void**)&map, g_map);

    init_edges_k<<<E_TOT / 256, 256>>>(ei, src, dst, valid);

    const int ntin_a[4] = {32768, 26240, 20992, 16800};
    const int n_a[4]    = {1024, 820, 656, 525};
    const int k_a[4]    = {820, 656, 525, 420};

    const float* hin = x;
    for (int l = 0; l < 4; l++) {
        int M = ntin_a[l];
        int n = n_a[l];
        int kk = k_a[l];
        int Mout = GQ * kk;

        cudaMemsetAsync(agg, 0, (size_t)M * HF * sizeof(float));
        cudaMemsetAsync(cnt, 0, (size_t)M * sizeof(float));
        cudaMemsetAsync(colsum, 0, HF * sizeof(float));
        cudaMemsetAsync(colsq, 0, HF * sizeof(float));

        scatter_agg_k<<<E_TOT / 8, 256>>>(hin, src, dst, valid, agg, cnt);
        mean_div_k<<<(M * HF + 255) / 256, 256>>>(agg, cnt, M * HF);
        gemm_dual_k<<<(M + 127) / 128, 256>>>(agg, hin, Wl[l], Wr[l], bb[l], h1, M);
        bn_partial_k<<<(M + 255) / 256, 128>>>(h1, M, colsum, colsq);
        bn_finalize_k<<<1, 128>>>(colsum, colsq, 1.0f / (float)M,
                                  gg[l], be[l], pp[l], scale, shift, invp);
        bn_relu_score_k<<<(M + 7) / 8, 256>>>(h1, M, scale, shift, pp[l], invp, score);

        cudaMemsetAsync(map, 0xFF, (size_t)M * sizeof(int));
        topk_k<<<GQ, 1024>>>(score, n, kk, map, perm);
        gather_gate_k<<<(Mout + 7) / 8, 256>>>(h1, perm, score, h0, Mout);
        readout_k<<<GQ, 128>>>(h0, kk, flat, l * 256);
        if (l < 3) remap_edges_k<<<E_TOT / 256, 256>>>(src, dst, valid, map);

        hin = h0;
    }

    dense1_k<<<GQ, 512>>>(flat, Wd1, bd1, hd);
    dense2_k<<<GQ, 512>>>(hd, Wd2, bd2, out);
}